// round 7
// baseline (speedup 1.0000x reference)
#include <cuda_runtime.h>
#include <math.h>

#define NUM_TASKS 1000
#define NF 256
#define NH 128
#define BATCH 4096
#define CHUNK 8

// Scratch (no allocations allowed) — grouping metadata
__device__ int g_off[NUM_TASKS + 1];
__device__ int g_order[BATCH];

// ---------------------------------------------------------------------------
// Fused prep: count + scan + scatter in ONE single-block kernel.
// ---------------------------------------------------------------------------
__global__ __launch_bounds__(1024) void prep_k(const int* __restrict__ task_ids, int n) {
    __shared__ int cnt[NUM_TASKS];     // counts, then reused as cursors
    __shared__ int sc[1024];
    int tid = threadIdx.x;

    for (int i = tid; i < NUM_TASKS; i += 1024) cnt[i] = 0;
    __syncthreads();

    for (int i = tid; i < n; i += 1024) atomicAdd(&cnt[task_ids[i]], 1);
    __syncthreads();

    sc[tid] = (tid < NUM_TASKS) ? cnt[tid] : 0;
    __syncthreads();
    for (int d = 1; d < 1024; d <<= 1) {
        int v = (tid >= d) ? sc[tid - d] : 0;
        __syncthreads();
        sc[tid] += v;
        __syncthreads();
    }
    if (tid < NUM_TASKS) {
        g_off[tid + 1] = sc[tid];
        if (tid == 0) g_off[0] = 0;
        cnt[tid] = (tid == 0) ? 0 : sc[tid - 1];   // cursor = exclusive start
    }
    __syncthreads();

    for (int i = tid; i < n; i += 1024) {
        int p = atomicAdd(&cnt[task_ids[i]], 1);
        g_order[p] = i;
    }
}

__device__ __forceinline__ float gelu_exact(float h) {
    return 0.5f * h * (1.0f + erff(h * 0.70710678118654752f));
}

// ---------------------------------------------------------------------------
// Chunk body, split-K across 2 thread-slices of 128 threads each.
// slice 0: f in [0,128), slice 1: f in [128,256). Partials combined in smem.
// Pad slots (s >= S) replicate sample 0; computed but never stored.
// ---------------------------------------------------------------------------
template<int SS>
__device__ __forceinline__ void do_chunk(
    int base, int S, int tid, int slice, int j,
    const float* __restrict__ x, const float* __restrict__ W,
    float b1, float w2, float b2,
    float (*sx)[NF], float (*hpart)[CHUNK][NH], int* sidx, float (*sred)[CHUNK],
    float* __restrict__ out)
{
    // Stage x: 256 threads cover the 256-float row exactly (one coalesced read)
    #pragma unroll
    for (int s = 0; s < SS; s++) {
        int src = base + ((s < S) ? s : 0);
        int ord = __ldg(&g_order[src]);
        if (tid == s) sidx[s] = ord;
        sx[s][tid] = x[(size_t)ord * NF + tid];
    }
    __syncthreads();

    float acc[SS];
    #pragma unroll
    for (int s = 0; s < SS; s++) acc[s] = 0.f;

    const float* __restrict__ Ws = W + (size_t)slice * (NF / 2) * NH;
    int fq0 = slice * (NF / 8);   // float4 index base into sx rows

    #pragma unroll 4
    for (int fq = 0; fq < NF / 8; fq++) {       // 32 iters: 4 f-rows each
        int f = fq * 4;
        float w_0 = Ws[(f + 0) * NH + j];
        float w_1 = Ws[(f + 1) * NH + j];
        float w_2 = Ws[(f + 2) * NH + j];
        float w_3 = Ws[(f + 3) * NH + j];
        #pragma unroll
        for (int s = 0; s < SS; s++) {
            float4 xv = ((const float4*)sx[s])[fq0 + fq];   // warp-broadcast
            acc[s] += xv.x * w_0 + xv.y * w_1 + xv.z * w_2 + xv.w * w_3;
        }
    }

    #pragma unroll
    for (int s = 0; s < SS; s++) hpart[slice][s][j] = acc[s];
    __syncthreads();

    // Layer 2 on first 128 threads: combine slices, gelu, weighted reduce
    if (tid < NH) {
        int lane = tid & 31, wid = tid >> 5;
        #pragma unroll
        for (int s = 0; s < SS; s++) {
            float h = hpart[0][s][j] + hpart[1][s][j] + b1;
            float v = gelu_exact(h) * w2;
            v += __shfl_xor_sync(0xffffffff, v, 16);
            v += __shfl_xor_sync(0xffffffff, v, 8);
            v += __shfl_xor_sync(0xffffffff, v, 4);
            v += __shfl_xor_sync(0xffffffff, v, 2);
            v += __shfl_xor_sync(0xffffffff, v, 1);
            if (lane == 0) sred[wid][s] = v;
        }
    }
    __syncthreads();

    if (tid < S) {
        float sum = sred[0][tid] + sred[1][tid] + sred[2][tid] + sred[3][tid];
        out[sidx[tid]] = sum + b2;
    }
    __syncthreads();   // protect sx/hpart/sred before next chunk
}

// One CTA per task, 256 threads (2 split-K slices x 128 hidden columns).
__global__ __launch_bounds__(256, 5) void mlp_k(
    const float* __restrict__ x,
    const float* __restrict__ l1_emb,
    const float* __restrict__ l1_bias,
    const float* __restrict__ l2_emb,
    const float* __restrict__ l2_bias,
    float* __restrict__ out)
{
    int t = blockIdx.x;
    int beg = g_off[t];
    int n   = g_off[t + 1] - beg;
    if (n == 0) return;

    int tid   = threadIdx.x;
    int slice = tid >> 7;          // 0 or 1
    int j     = tid & 127;         // hidden column

    const float* __restrict__ W = l1_emb + (size_t)t * (NF * NH);
    float b1 = l1_bias[t * NH + j];
    float w2 = l2_emb[t * NH + j];
    float b2 = l2_bias[t];

    __shared__ float sx[CHUNK][NF];           // 8 KB
    __shared__ float hpart[2][CHUNK][NH];     // 8 KB
    __shared__ int   sidx[CHUNK];
    __shared__ float sred[4][CHUNK];

    int pos = beg, rem = n;
    while (rem > 0) {
        if (rem > 4) {
            do_chunk<8>(pos, min(rem, 8), tid, slice, j, x, W, b1, w2, b2,
                        sx, hpart, sidx, sred, out);
            pos += 8; rem -= 8;
        } else if (rem > 2) {
            do_chunk<4>(pos, rem, tid, slice, j, x, W, b1, w2, b2,
                        sx, hpart, sidx, sred, out);
            rem = 0;
        } else {
            do_chunk<2>(pos, rem, tid, slice, j, x, W, b1, w2, b2,
                        sx, hpart, sidx, sred, out);
            rem = 0;
        }
    }
}

extern "C" void kernel_launch(void* const* d_in, const int* in_sizes, int n_in,
                              void* d_out, int out_size) {
    const float* x       = (const float*)d_in[0];
    const int*   task_id = (const int*)  d_in[1];
    const float* l1_emb  = (const float*)d_in[2];
    const float* l1_bias = (const float*)d_in[3];
    const float* l2_emb  = (const float*)d_in[4];
    const float* l2_bias = (const float*)d_in[5];
    float* out = (float*)d_out;

    int nb = in_sizes[1];  // BATCH

    prep_k<<<1, 1024>>>(task_id, nb);
    mlp_k<<<NUM_TASKS, 256>>>(x, l1_emb, l1_bias, l2_emb, l2_bias, out);
}

// round 10
// speedup vs baseline: 1.3724x; 1.3724x over previous
#include <cuda_runtime.h>
#include <math.h>

#define NUM_TASKS 1000
#define NF 256
#define NH 128
#define BATCH 4096
#define CHUNK 8

// Scratch (no allocations allowed) — grouping metadata
__device__ int g_off[NUM_TASKS + 1];
__device__ int g_order[BATCH];

// ---------------------------------------------------------------------------
// Fused prep: count + scan + scatter in ONE single-block kernel.
// ---------------------------------------------------------------------------
__global__ __launch_bounds__(1024) void prep_k(const int* __restrict__ task_ids, int n) {
    __shared__ int cnt[NUM_TASKS];
    __shared__ int sc[1024];
    int tid = threadIdx.x;

    for (int i = tid; i < NUM_TASKS; i += 1024) cnt[i] = 0;
    __syncthreads();
    for (int i = tid; i < n; i += 1024) atomicAdd(&cnt[task_ids[i]], 1);
    __syncthreads();

    sc[tid] = (tid < NUM_TASKS) ? cnt[tid] : 0;
    __syncthreads();
    for (int d = 1; d < 1024; d <<= 1) {
        int v = (tid >= d) ? sc[tid - d] : 0;
        __syncthreads();
        sc[tid] += v;
        __syncthreads();
    }
    if (tid < NUM_TASKS) {
        g_off[tid + 1] = sc[tid];
        if (tid == 0) g_off[0] = 0;
        cnt[tid] = (tid == 0) ? 0 : sc[tid - 1];
    }
    __syncthreads();

    for (int i = tid; i < n; i += 1024) {
        int p = atomicAdd(&cnt[task_ids[i]], 1);
        g_order[p] = i;
    }
}

__device__ __forceinline__ float gelu_exact(float h) {
    return 0.5f * h * (1.0f + erff(h * 0.70710678118654752f));
}

// ---------------------------------------------------------------------------
// Chunk body. 256 threads = 8 warp-groups (wg = tid>>5, 0..7), each wg streams
// 32 contiguous W rows; within a warp, lane owns hidden cols 4*lane..4*lane+3
// loaded as float4 (LDG.128, 512B/warp/instruction). 8 partial-h fragments
// combined in smem, then layer-2 on first 128 threads.
// Pad slots (s >= S) replicate sample 0; computed but never stored.
// ---------------------------------------------------------------------------
template<int SS>
__device__ __forceinline__ void do_chunk(
    int base, int S, int tid, int wg, int lane, int j,
    const float* __restrict__ x, const float* __restrict__ W,
    float b1, float w2, float b2,
    float (*sx)[NF], float (*hpart)[CHUNK][NH], int* sidx, float (*sred)[CHUNK],
    float* __restrict__ out)
{
    // Stage x: 256 threads cover a 256-float row exactly (coalesced)
    #pragma unroll
    for (int s = 0; s < SS; s++) {
        int src = base + ((s < S) ? s : 0);
        int ord = __ldg(&g_order[src]);
        if (tid == s) sidx[s] = ord;
        sx[s][tid] = x[(size_t)ord * NF + tid];
    }
    __syncthreads();

    int f0 = wg * 32;                       // this warp-group's 32 W rows
    const float4* __restrict__ Wv =
        (const float4*)(W + (size_t)f0 * NH) + lane;   // row stride = NH/4 = 32 float4

    float4 acc[SS];
    #pragma unroll
    for (int s = 0; s < SS; s++) acc[s] = make_float4(0.f, 0.f, 0.f, 0.f);

    #pragma unroll 8
    for (int r = 0; r < 32; r++) {
        float4 wv = Wv[r * 32];             // LDG.128
        const float* sxf = &sx[0][f0 + r];
        #pragma unroll
        for (int s = 0; s < SS; s++) {
            float xs = sxf[s * NF];         // smem broadcast
            acc[s].x += xs * wv.x;
            acc[s].y += xs * wv.y;
            acc[s].z += xs * wv.z;
            acc[s].w += xs * wv.w;
        }
    }

    // Write partial h fragments (float4 store, conflict-free: lane*16B)
    #pragma unroll
    for (int s = 0; s < SS; s++)
        *(float4*)&hpart[wg][s][lane * 4] = acc[s];
    __syncthreads();

    // Layer 2 on first 128 threads: combine 8 fragments, gelu, weighted reduce
    if (tid < NH) {
        int l2lane = tid & 31, l2wid = tid >> 5;
        #pragma unroll
        for (int s = 0; s < SS; s++) {
            float h = b1;
            #pragma unroll
            for (int g = 0; g < 8; g++) h += hpart[g][s][j];
            float v = gelu_exact(h) * w2;
            v += __shfl_xor_sync(0xffffffff, v, 16);
            v += __shfl_xor_sync(0xffffffff, v, 8);
            v += __shfl_xor_sync(0xffffffff, v, 4);
            v += __shfl_xor_sync(0xffffffff, v, 2);
            v += __shfl_xor_sync(0xffffffff, v, 1);
            if (l2lane == 0) sred[l2wid][s] = v;
        }
    }
    __syncthreads();

    if (tid < S) {
        float sum = sred[0][tid] + sred[1][tid] + sred[2][tid] + sred[3][tid];
        out[sidx[tid]] = sum + b2;
    }
    __syncthreads();   // protect sx/hpart/sred before next chunk
}

// One CTA per task, 256 threads.
__global__ __launch_bounds__(256, 3) void mlp_k(
    const float* __restrict__ x,
    const float* __restrict__ l1_emb,
    const float* __restrict__ l1_bias,
    const float* __restrict__ l2_emb,
    const float* __restrict__ l2_bias,
    float* __restrict__ out)
{
    int t = blockIdx.x;
    int beg = g_off[t];
    int n   = g_off[t + 1] - beg;
    if (n == 0) return;

    int tid  = threadIdx.x;
    int wg   = tid >> 5;           // warp-group 0..7 (f-row block)
    int lane = tid & 31;           // hidden col group: cols 4*lane..4*lane+3
    int j    = tid & 127;          // layer-2 hidden column

    const float* __restrict__ W = l1_emb + (size_t)t * (NF * NH);
    float b1 = l1_bias[t * NH + j];
    float w2 = l2_emb[t * NH + j];
    float b2 = l2_bias[t];

    __shared__ float sx[CHUNK][NF];           // 8 KB
    __shared__ float hpart[8][CHUNK][NH];     // 32 KB
    __shared__ int   sidx[CHUNK];
    __shared__ float sred[4][CHUNK];

    int pos = beg, rem = n;
    while (rem > 0) {
        if (rem > 4) {
            do_chunk<8>(pos, min(rem, 8), tid, wg, lane, j, x, W, b1, w2, b2,
                        sx, hpart, sidx, sred, out);
            pos += 8; rem -= 8;
        } else if (rem > 2) {
            do_chunk<4>(pos, rem, tid, wg, lane, j, x, W, b1, w2, b2,
                        sx, hpart, sidx, sred, out);
            rem = 0;
        } else {
            do_chunk<2>(pos, rem, tid, wg, lane, j, x, W, b1, w2, b2,
                        sx, hpart, sidx, sred, out);
            rem = 0;
        }
    }
}

extern "C" void kernel_launch(void* const* d_in, const int* in_sizes, int n_in,
                              void* d_out, int out_size) {
    const float* x       = (const float*)d_in[0];
    const int*   task_id = (const int*)  d_in[1];
    const float* l1_emb  = (const float*)d_in[2];
    const float* l1_bias = (const float*)d_in[3];
    const float* l2_emb  = (const float*)d_in[4];
    const float* l2_bias = (const float*)d_in[5];
    float* out = (float*)d_out;

    int nb = in_sizes[1];  // BATCH

    prep_k<<<1, 1024>>>(task_id, nb);
    mlp_k<<<NUM_TASKS, 256>>>(x, l1_emb, l1_bias, l2_emb, l2_bias, out);
}